// round 8
// baseline (speedup 1.0000x reference)
#include <cuda_runtime.h>
#include <cuda_fp16.h>
#include <cstdint>

#define SEQ 4096
#define EMB 1024

// ---------------- scratch (static, allocation-free) ----------------
__device__ __half g_Xh [(size_t)SEQ * EMB];
__device__ __half g_Wqt[(size_t)EMB * EMB];
__device__ __half g_Wkt[(size_t)EMB * EMB];
__device__ __half g_Wvt[(size_t)EMB * EMB];
__device__ __half g_Qh [(size_t)SEQ * EMB];
__device__ __half g_Kh [(size_t)SEQ * EMB];
__device__ __half g_Vh [(size_t)SEQ * EMB];
__device__ __half g_Vt [(size_t)EMB * SEQ];
__device__ __half g_Sh [(size_t)SEQ * SEQ];
__device__ float  g_part[(size_t)SEQ * 64];   // per (row, colCTA*2+wn) partials
__device__ float  g_rsum[SEQ];                // 1 / rowsum

// ---------------- helpers ----------------
__device__ __forceinline__ uint32_t smem_u32(const void* p) {
    return (uint32_t)__cvta_generic_to_shared(p);
}
__device__ __forceinline__ void cp16(uint32_t s, const void* g) {
    asm volatile("cp.async.cg.shared.global [%0], [%1], 16;" :: "r"(s), "l"(g));
}
__device__ __forceinline__ void cp_commit() {
    asm volatile("cp.async.commit_group;" ::: "memory");
}
template <int N>
__device__ __forceinline__ void cp_wait() {
    asm volatile("cp.async.wait_group %0;" :: "n"(N) : "memory");
}
__device__ __forceinline__ float ex2_mufu(float y) {
    float r;
    asm("ex2.approx.ftz.f32 %0, %1;" : "=f"(r) : "f"(y));
    return r;
}
// exact-split exp2 on the FMA pipe (y = n + f, f in [-.5,.5], degree-5 poly)
__device__ __forceinline__ float ex2_fma(float y) {
    const float MAGIC = 12582912.0f;          // 1.5 * 2^23
    float tm = __fadd_rn(y, MAGIC);
    float f  = __fadd_rn(y, -__fadd_rn(tm, -MAGIC));
    int   eb = (__float_as_int(tm) << 23) + 0x3F800000;
    float pl = 0.0013333558f;
    pl = fmaf(pl, f, 0.0096181291f);
    pl = fmaf(pl, f, 0.0555041087f);
    pl = fmaf(pl, f, 0.2402265069f);
    pl = fmaf(pl, f, 0.6931471806f);
    pl = fmaf(pl, f, 1.0f);
    return __int_as_float(eb) * pl;
}
// m16n8k16 fp16 MMA, fp32 accumulate
__device__ __forceinline__ void mma_f16(
    float& c0, float& c1, float& c2, float& c3,
    uint32_t a0, uint32_t a1, uint32_t a2, uint32_t a3,
    uint32_t b0, uint32_t b1)
{
    asm volatile(
        "mma.sync.aligned.m16n8k16.row.col.f32.f16.f16.f32 "
        "{%0,%1,%2,%3}, {%4,%5,%6,%7}, {%8,%9}, {%0,%1,%2,%3};"
        : "+f"(c0), "+f"(c1), "+f"(c2), "+f"(c3)
        : "r"(a0), "r"(a1), "r"(a2), "r"(a3), "r"(b0), "r"(b1));
}
__device__ __forceinline__ void ldsm4(uint32_t& r0, uint32_t& r1,
                                      uint32_t& r2, uint32_t& r3, uint32_t a)
{
    asm volatile("ldmatrix.sync.aligned.m8n8.x4.shared.b16 {%0,%1,%2,%3}, [%4];"
                 : "=r"(r0), "=r"(r1), "=r"(r2), "=r"(r3) : "r"(a));
}

// ---------------------------------------------------------------------------
// FP16 tensor-core NT GEMM: C[M,N] = f( A[M,K] @ B[N,K]^T )
// 128 threads (4 warps 2x2), warp tile 64x64, CTA tile 128x128, BK=64,
// 3-stage cp.async, one __syncthreads/iter, XOR-swizzled smem,
// ldmatrix.x4 fragment loads (8 LDSM per warp per k16).
// MODE 0: fp16 out (projections)
// MODE 1: Sh = fp16(exp(alpha*acc)); per-(row,warp) partial sums -> part
// MODE 2: fp32 out scaled by alpha * rsum[row]   (rsum = reciprocal)
// ---------------------------------------------------------------------------
#define STG 3
#define OPW (128 * 32)                 // fp16x2 words per operand tile (16KB)
#define STW (2 * OPW)
#define GEMM_DYNSMEM (STG * STW * 4)   // 98304 bytes

template <int MODE>
__device__ __forceinline__ void gemm_body(
    const __half* __restrict__ A, const __half* __restrict__ B,
    void* __restrict__ Cv, int N, int K, float alpha,
    const float* __restrict__ rsum, float* __restrict__ part,
    int bm, int bn, int bx)
{
    extern __shared__ uint32_t sm[];

    const int tid  = threadIdx.x;
    const int warp = tid >> 5;
    const int lane = tid & 31;
    const int g    = lane >> 2;
    const int t    = lane & 3;
    const int wm   = warp & 1;      // 2 x 64 rows
    const int wn   = warp >> 1;     // 2 x 64 cols

    float acc[4][8][4];
    #pragma unroll
    for (int mi = 0; mi < 4; mi++)
        #pragma unroll
        for (int ni = 0; ni < 8; ni++)
            #pragma unroll
            for (int r = 0; r < 4; r++) acc[mi][ni][r] = 0.0f;

    const uint32_t smb = smem_u32(sm);
    const int lrow = tid >> 3;          // 0..15, 8 passes -> 128 rows
    const int lseg = tid & 7;

    auto load_stage = [&](int chunk) {
        const int s  = chunk % STG;
        const int k0 = chunk * 64;
        const uint32_t sa = smb + s * (STW * 4);
        const uint32_t sb = sa + OPW * 4;
        #pragma unroll
        for (int p = 0; p < 8; p++) {
            const int row  = lrow + p * 16;
            const int segS = lseg ^ (row & 7);
            const uint32_t so = (uint32_t)(row * 128 + segS * 16);
            cp16(sa + so, A + (size_t)(bm + row) * K + k0 + lseg * 8);
            cp16(sb + so, B + (size_t)(bn + row) * K + k0 + lseg * 8);
        }
        cp_commit();
    };

    const int NT = K >> 6;

    load_stage(0);
    load_stage(1);

    // ldmatrix per-lane geometry
    const int rl = lane & 15;            // row within 16-row tile
    const int hh = lane >> 4;            // k-chunk select (0/1)
    const uint32_t swzb = (uint32_t)((rl & 7) * 4);
    uint32_t rowOffA[4], rowOffB[4];
    #pragma unroll
    for (int i4 = 0; i4 < 4; i4++) {
        rowOffA[i4] = (uint32_t)((wm * 64 + i4 * 16 + rl) * 128);
        rowOffB[i4] = (uint32_t)((wn * 64 + i4 * 16 + rl) * 128);
    }

    for (int i = 0; i < NT; i++) {
        const int s = i % STG;
        cp_wait<1>();
        __syncthreads();

        if (i + 2 < NT) load_stage(i + 2);
        else            cp_commit();

        const uint32_t aBase = smb + s * (STW * 4);
        const uint32_t bBase = aBase + OPW * 4;

        #pragma unroll
        for (int ksi = 0; ksi < 4; ksi++) {
            const uint32_t off =
                (((uint32_t)(8 * ksi + 4 * hh) ^ swzb) << 2);

            uint32_t af[4][4];
            #pragma unroll
            for (int mi = 0; mi < 4; mi++)
                ldsm4(af[mi][0], af[mi][1], af[mi][2], af[mi][3],
                      aBase + rowOffA[mi] + off);

            uint32_t bq[4][4];    // [nj][ M0=b(2nj)k0, M1=b(2nj+1)k0,
                                  //       M2=b(2nj)k1, M3=b(2nj+1)k1 ]
            #pragma unroll
            for (int nj = 0; nj < 4; nj++)
                ldsm4(bq[nj][0], bq[nj][1], bq[nj][2], bq[nj][3],
                      bBase + rowOffB[nj] + off);

            #pragma unroll
            for (int mi = 0; mi < 4; mi++)
                #pragma unroll
                for (int ni = 0; ni < 8; ni++) {
                    const uint32_t b0 = bq[ni >> 1][(ni & 1)];
                    const uint32_t b1 = bq[ni >> 1][(ni & 1) + 2];
                    mma_f16(acc[mi][ni][0], acc[mi][ni][1],
                            acc[mi][ni][2], acc[mi][ni][3],
                            af[mi][0], af[mi][1], af[mi][2], af[mi][3],
                            b0, b1);
                }
        }
    }

    // ---- epilogue ----
    if (MODE == 0) {
        __half* C = (__half*)Cv;
        #pragma unroll
        for (int mi = 0; mi < 4; mi++) {
            const int row = bm + wm * 64 + mi * 16 + g;
            #pragma unroll
            for (int ni = 0; ni < 8; ni++) {
                const int col = bn + wn * 64 + ni * 8 + 2 * t;
                *reinterpret_cast<__half2*>(&C[(size_t)row * N + col]) =
                    __floats2half2_rn(acc[mi][ni][0], acc[mi][ni][1]);
                *reinterpret_cast<__half2*>(&C[(size_t)(row + 8) * N + col]) =
                    __floats2half2_rn(acc[mi][ni][2], acc[mi][ni][3]);
            }
        }
    } else if (MODE == 1) {
        __half* C = (__half*)Cv;
        const float aL = alpha * 1.4426950408889634f;   // alpha * log2(e)
        #pragma unroll
        for (int mi = 0; mi < 4; mi++) {
            const int row = bm + wm * 64 + mi * 16 + g;
            float sr0 = 0.0f, sr1 = 0.0f;
            #pragma unroll
            for (int ni = 0; ni < 8; ni++) {
                const int col = bn + wn * 64 + ni * 8 + 2 * t;
                float v0, v1, v2, v3;
                if (ni & 1) {                 // FMA pipe
                    v0 = ex2_fma(acc[mi][ni][0] * aL);
                    v1 = ex2_fma(acc[mi][ni][1] * aL);
                    v2 = ex2_fma(acc[mi][ni][2] * aL);
                    v3 = ex2_fma(acc[mi][ni][3] * aL);
                } else {                      // MUFU pipe
                    v0 = ex2_mufu(acc[mi][ni][0] * aL);
                    v1 = ex2_mufu(acc[mi][ni][1] * aL);
                    v2 = ex2_mufu(acc[mi][ni][2] * aL);
                    v3 = ex2_mufu(acc[mi][ni][3] * aL);
                }
                *reinterpret_cast<__half2*>(&C[(size_t)row * N + col]) =
                    __floats2half2_rn(v0, v1);
                *reinterpret_cast<__half2*>(&C[(size_t)(row + 8) * N + col]) =
                    __floats2half2_rn(v2, v3);
                sr0 += v0 + v1;
                sr1 += v2 + v3;
            }
            // sum over the 4 t-lanes (same g)
            sr0 += __shfl_xor_sync(0xFFFFFFFF, sr0, 1);
            sr0 += __shfl_xor_sync(0xFFFFFFFF, sr0, 2);
            sr1 += __shfl_xor_sync(0xFFFFFFFF, sr1, 1);
            sr1 += __shfl_xor_sync(0xFFFFFFFF, sr1, 2);
            if (t == 0) {
                part[(size_t)row * 64 + bx * 2 + wn]       = sr0;
                part[(size_t)(row + 8) * 64 + bx * 2 + wn] = sr1;
            }
        }
    } else {
        float* C = (float*)Cv;
        #pragma unroll
        for (int mi = 0; mi < 4; mi++) {
            const int row = bm + wm * 64 + mi * 16 + g;
            const float s0 = alpha * __ldg(&rsum[row]);
            const float s1 = alpha * __ldg(&rsum[row + 8]);
            #pragma unroll
            for (int ni = 0; ni < 8; ni++) {
                const int col = bn + wn * 64 + ni * 8 + 2 * t;
                *reinterpret_cast<float2*>(&C[(size_t)row * N + col]) =
                    make_float2(acc[mi][ni][0] * s0, acc[mi][ni][1] * s0);
                *reinterpret_cast<float2*>(&C[(size_t)(row + 8) * N + col]) =
                    make_float2(acc[mi][ni][2] * s1, acc[mi][ni][3] * s1);
            }
        }
    }
}

// Fused Q/K/V projections (fp16 out), blockIdx.z selects weight/output.
__global__ void __launch_bounds__(128, 2) proj_k(
    const __half* __restrict__ Xh,
    const __half* __restrict__ B0, const __half* __restrict__ B1,
    const __half* __restrict__ B2,
    __half* __restrict__ C0, __half* __restrict__ C1, __half* __restrict__ C2)
{
    const int z = blockIdx.z;
    const __half* B = (z == 0) ? B0 : (z == 1) ? B1 : B2;
    __half*       C = (z == 0) ? C0 : (z == 1) ? C1 : C2;
    gemm_body<0>(Xh, B, C, EMB, EMB, 1.0f, nullptr, nullptr,
                 blockIdx.y * 128, blockIdx.x * 128, blockIdx.x);
}

// Score GEMM with fused exp + partial row sums.
__global__ void __launch_bounds__(128, 2) score_k(
    const __half* __restrict__ Q, const __half* __restrict__ Kh,
    __half* __restrict__ Sh, float* __restrict__ part)
{
    gemm_body<1>(Q, Kh, Sh, SEQ, EMB, 0.03125f, nullptr, part,
                 blockIdx.y * 128, blockIdx.x * 128, blockIdx.x);
}

// PV GEMM with 1/rowsum epilogue scaling.
__global__ void __launch_bounds__(128, 2) pv_k(
    const __half* __restrict__ Sh, const __half* __restrict__ Vt,
    float* __restrict__ out, const float* __restrict__ rsum)
{
    gemm_body<2>(Sh, Vt, out, EMB, SEQ, 1.0f, rsum, nullptr,
                 blockIdx.y * 128, blockIdx.x * 128, blockIdx.x);
}

// ---------------------------------------------------------------------------
// rowsum reduce: rsum[row] = 1 / sum(part[row][0..63])
// ---------------------------------------------------------------------------
__global__ void __launch_bounds__(256) rsum_k(const float* __restrict__ part,
                                              float* __restrict__ rsum)
{
    const int row = blockIdx.x * 256 + threadIdx.x;
    const float4* p = reinterpret_cast<const float4*>(part + (size_t)row * 64);
    float s = 0.0f;
    #pragma unroll
    for (int i = 0; i < 16; i++) {
        float4 v = p[i];
        s += (v.x + v.y) + (v.z + v.w);
    }
    rsum[row] = 1.0f / s;
}

// ---------------------------------------------------------------------------
// x fp32 -> fp16
// ---------------------------------------------------------------------------
__global__ void __launch_bounds__(256) cvtx_kernel(const float* __restrict__ in,
                                                   __half* __restrict__ out, int n4)
{
    int i = blockIdx.x * 256 + threadIdx.x;
    if (i < n4) {
        float4 v = reinterpret_cast<const float4*>(in)[i];
        __half2* o = reinterpret_cast<__half2*>(out) + i * 2;
        o[0] = __floats2half2_rn(v.x, v.y);
        o[1] = __floats2half2_rn(v.z, v.w);
    }
}

// ---------------------------------------------------------------------------
// Fused transpose of the 3 fp32 weight matrices -> fp16 (blockIdx.z selects).
// ---------------------------------------------------------------------------
__global__ void __launch_bounds__(256) wtrans_k(
    const float* __restrict__ Wq, const float* __restrict__ Wk,
    const float* __restrict__ Wv,
    __half* __restrict__ Tq, __half* __restrict__ Tk, __half* __restrict__ Tv)
{
    __shared__ float t[32][33];
    const int z = blockIdx.z;
    const float* in = (z == 0) ? Wq : (z == 1) ? Wk : Wv;
    __half*     out = (z == 0) ? Tq : (z == 1) ? Tk : Tv;

    const int bx = blockIdx.x * 32, by = blockIdx.y * 32;
    const int x = threadIdx.x, y = threadIdx.y;     // 32 x 8
    #pragma unroll
    for (int j = 0; j < 32; j += 8)
        t[y + j][x] = in[(size_t)(by + y + j) * EMB + bx + x];
    __syncthreads();
    #pragma unroll
    for (int j = 0; j < 32; j += 8)
        out[(size_t)(bx + y + j) * EMB + by + x] = __float2half(t[x][y + j]);
}

// ---------------------------------------------------------------------------
// fp16 transpose (V -> V^T)
// ---------------------------------------------------------------------------
__global__ void __launch_bounds__(256) htrans_k(const __half* __restrict__ in,
                                                __half* __restrict__ out,
                                                int R, int C)
{
    __shared__ __half t[32][34];
    const int bx = blockIdx.x * 32, by = blockIdx.y * 32;
    const int x = threadIdx.x, y = threadIdx.y;
    #pragma unroll
    for (int j = 0; j < 32; j += 8)
        t[y + j][x] = in[(size_t)(by + y + j) * C + bx + x];
    __syncthreads();
    #pragma unroll
    for (int j = 0; j < 32; j += 8)
        out[(size_t)(bx + y + j) * R + by + x] = t[x][y + j];
}

// ---------------------------------------------------------------------------
extern "C" void kernel_launch(void* const* d_in, const int* in_sizes, int n_in,
                              void* d_out, int out_size)
{
    const float* x  = (const float*)d_in[0];
    const float* Wq = (const float*)d_in[1];
    const float* Wk = (const float*)d_in[2];
    const float* Wv = (const float*)d_in[3];
    float* out = (float*)d_out;

    __half *Xh, *Wqt, *Wkt, *Wvt, *Qh, *Kh, *Vh, *Vt, *Sh;
    float *Part, *Rs;
    cudaGetSymbolAddress((void**)&Xh,  g_Xh);
    cudaGetSymbolAddress((void**)&Wqt, g_Wqt);
    cudaGetSymbolAddress((void**)&Wkt, g_Wkt);
    cudaGetSymbolAddress((void**)&Wvt, g_Wvt);
    cudaGetSymbolAddress((void**)&Qh,  g_Qh);
    cudaGetSymbolAddress((void**)&Kh,  g_Kh);
    cudaGetSymbolAddress((void**)&Vh,  g_Vh);
    cudaGetSymbolAddress((void**)&Vt,  g_Vt);
    cudaGetSymbolAddress((void**)&Sh,  g_Sh);
    cudaGetSymbolAddress((void**)&Part, g_part);
    cudaGetSymbolAddress((void**)&Rs,  g_rsum);

    cudaFuncSetAttribute(proj_k,
        cudaFuncAttributeMaxDynamicSharedMemorySize, GEMM_DYNSMEM);
    cudaFuncSetAttribute(score_k,
        cudaFuncAttributeMaxDynamicSharedMemorySize, GEMM_DYNSMEM);
    cudaFuncSetAttribute(pv_k,
        cudaFuncAttributeMaxDynamicSharedMemorySize, GEMM_DYNSMEM);

    const dim3 tblk(32, 8);
    const dim3 gW(EMB / 32, EMB / 32, 3);
    const dim3 gVt(EMB / 32, SEQ / 32);

    // Operand prep.
    cvtx_kernel<<<(SEQ * EMB / 4 + 255) / 256, 256>>>(x, Xh, SEQ * EMB / 4);
    wtrans_k<<<gW, tblk>>>(Wq, Wk, Wv, Wqt, Wkt, Wvt);

    const dim3 blk(128);
    const dim3 gProj(EMB / 128, SEQ / 128, 3);
    const dim3 gOne (EMB / 128, SEQ / 128);
    const dim3 gScore(SEQ / 128, SEQ / 128);

    // Projections (NT, fp16 out).
    proj_k<<<gProj, blk, GEMM_DYNSMEM>>>(Xh, Wqt, Wkt, Wvt, Qh, Kh, Vh);

    // V^T for the NT PV GEMM.
    htrans_k<<<gVt, tblk>>>(Vh, Vt, SEQ, EMB);

    // Scores + fused exp (fp16 out) + deterministic partial row sums.
    score_k<<<gScore, blk, GEMM_DYNSMEM>>>(Qh, Kh, Sh, Part);

    // Reduce partials -> reciprocal row sums.
    rsum_k<<<SEQ / 256, 256>>>(Part, Rs);

    // Output: out = diag(1/rowsum) * (expS @ Vt^T).
    pv_k<<<gOne, blk, GEMM_DYNSMEM>>>(Sh, Vt, out, Rs);
}

// round 9
// speedup vs baseline: 1.0904x; 1.0904x over previous
#include <cuda_runtime.h>
#include <cuda_fp16.h>
#include <cstdint>

#define SEQ 4096
#define EMB 1024

// ---------------- scratch (static, allocation-free) ----------------
__device__ __half g_Xh [(size_t)SEQ * EMB];
__device__ __half g_Wqt[(size_t)EMB * EMB];
__device__ __half g_Wkt[(size_t)EMB * EMB];
__device__ __half g_Wvt[(size_t)EMB * EMB];
__device__ __half g_Qh [(size_t)SEQ * EMB];
__device__ __half g_Kh [(size_t)SEQ * EMB];
__device__ __half g_Vh [(size_t)SEQ * EMB];
__device__ __half g_Vt [(size_t)EMB * SEQ];
__device__ __half g_Sh [(size_t)SEQ * SEQ];
__device__ float  g_part[(size_t)SEQ * 64];   // per (row, colCTA*2+wn) partials

// ---------------- helpers ----------------
__device__ __forceinline__ uint32_t smem_u32(const void* p) {
    return (uint32_t)__cvta_generic_to_shared(p);
}
__device__ __forceinline__ void cp16(uint32_t s, const void* g) {
    asm volatile("cp.async.cg.shared.global [%0], [%1], 16;" :: "r"(s), "l"(g));
}
__device__ __forceinline__ void cp_commit() {
    asm volatile("cp.async.commit_group;" ::: "memory");
}
template <int N>
__device__ __forceinline__ void cp_wait() {
    asm volatile("cp.async.wait_group %0;" :: "n"(N) : "memory");
}
__device__ __forceinline__ float ex2_mufu(float y) {
    float r;
    asm("ex2.approx.ftz.f32 %0, %1;" : "=f"(r) : "f"(y));
    return r;
}
// exact-split exp2 on the FMA pipe (y = n + f, f in [-.5,.5], degree-5 poly)
__device__ __forceinline__ float ex2_fma(float y) {
    const float MAGIC = 12582912.0f;          // 1.5 * 2^23
    float tm = __fadd_rn(y, MAGIC);
    float f  = __fadd_rn(y, -__fadd_rn(tm, -MAGIC));
    int   eb = (__float_as_int(tm) << 23) + 0x3F800000;
    float pl = 0.0013333558f;
    pl = fmaf(pl, f, 0.0096181291f);
    pl = fmaf(pl, f, 0.0555041087f);
    pl = fmaf(pl, f, 0.2402265069f);
    pl = fmaf(pl, f, 0.6931471806f);
    pl = fmaf(pl, f, 1.0f);
    return __int_as_float(eb) * pl;
}
// m16n8k16 fp16 MMA, fp32 accumulate
__device__ __forceinline__ void mma_f16(
    float& c0, float& c1, float& c2, float& c3,
    uint32_t a0, uint32_t a1, uint32_t a2, uint32_t a3,
    uint32_t b0, uint32_t b1)
{
    asm volatile(
        "mma.sync.aligned.m16n8k16.row.col.f32.f16.f16.f32 "
        "{%0,%1,%2,%3}, {%4,%5,%6,%7}, {%8,%9}, {%0,%1,%2,%3};"
        : "+f"(c0), "+f"(c1), "+f"(c2), "+f"(c3)
        : "r"(a0), "r"(a1), "r"(a2), "r"(a3), "r"(b0), "r"(b1));
}

// ---------------------------------------------------------------------------
// FP16 tensor-core NT GEMM: C[M,N] = f( A[M,K] @ B[N,K]^T )
// 128 threads (4 warps 2x2), warp tile 64x64, CTA tile 128x128, BK=64,
// 3-stage cp.async, one __syncthreads/iter, XOR-swizzled smem,
// scalar-LDS fragment loads (round-7 known-good mainloop).
// MODE 0: fp16 out (projections)
// MODE 1: Sh = fp16(exp(alpha*acc)); per-(row,warp) partial sums -> part
// MODE 2: fp32 out scaled by rsum computed in prologue from part
// ---------------------------------------------------------------------------
#define STG 3
#define OPW (128 * 32)                 // fp16x2 words per operand tile (16KB)
#define STW (2 * OPW)
#define GEMM_DYNSMEM (STG * STW * 4)   // 98304 bytes

template <int MODE>
__device__ __forceinline__ void gemm_body(
    const __half* __restrict__ A, const __half* __restrict__ B,
    void* __restrict__ Cv, int N, int K, float alpha,
    float* __restrict__ part, int bm, int bn, int bx)
{
    extern __shared__ uint32_t sm[];
    __shared__ float rsm[128];

    const int tid  = threadIdx.x;
    const int warp = tid >> 5;
    const int lane = tid & 31;
    const int g    = lane >> 2;
    const int t    = lane & 3;
    const int wm   = warp & 1;      // 2 x 64 rows
    const int wn   = warp >> 1;     // 2 x 64 cols

    // MODE 2 prologue: reciprocal row sums for this CTA's 128 rows
    // (fixed-order 64-term sum -> deterministic). Covered by iter-0 barrier.
    if (MODE == 2) {
        const float4* pp = reinterpret_cast<const float4*>(
            part + (size_t)(bm + tid) * 64);
        float s = 0.0f;
        #pragma unroll
        for (int i = 0; i < 16; i++) {
            float4 v = pp[i];
            s += (v.x + v.y) + (v.z + v.w);
        }
        rsm[tid] = 1.0f / s;
    }

    float acc[4][8][4];
    #pragma unroll
    for (int mi = 0; mi < 4; mi++)
        #pragma unroll
        for (int ni = 0; ni < 8; ni++)
            #pragma unroll
            for (int r = 0; r < 4; r++) acc[mi][ni][r] = 0.0f;

    const uint32_t smb = smem_u32(sm);
    const int lrow = tid >> 3;          // 0..15, 8 passes -> 128 rows
    const int lseg = tid & 7;

    auto load_stage = [&](int chunk) {
        const int s  = chunk % STG;
        const int k0 = chunk * 64;
        const uint32_t sa = smb + s * (STW * 4);
        const uint32_t sb = sa + OPW * 4;
        #pragma unroll
        for (int p = 0; p < 8; p++) {
            const int row  = lrow + p * 16;
            const int segS = lseg ^ (row & 7);
            const uint32_t so = (uint32_t)(row * 128 + segS * 16);
            cp16(sa + so, A + (size_t)(bm + row) * K + k0 + lseg * 8);
            cp16(sb + so, B + (size_t)(bn + row) * K + k0 + lseg * 8);
        }
        cp_commit();
    };

    const int NT = K >> 6;

    load_stage(0);
    load_stage(1);

    for (int i = 0; i < NT; i++) {
        const int s = i % STG;
        cp_wait<1>();
        __syncthreads();

        if (i + 2 < NT) load_stage(i + 2);
        else            cp_commit();

        const uint32_t* As  = sm + s * STW;
        const uint32_t* Bsm = As + OPW;
        const int swz = 4 * g;

        #pragma unroll
        for (int ksi = 0; ksi < 4; ksi++) {
            const int c0 = (ksi * 8 + t)     ^ swz;
            const int c2 = (ksi * 8 + t + 4) ^ swz;

            uint32_t af[4][4];
            #pragma unroll
            for (int mi = 0; mi < 4; mi++) {
                const uint32_t* base = As + (wm * 64 + mi * 16 + g) * 32;
                af[mi][0] = base[c0];
                af[mi][1] = base[8 * 32 + c0];
                af[mi][2] = base[c2];
                af[mi][3] = base[8 * 32 + c2];
            }
            uint32_t bf[8][2];
            #pragma unroll
            for (int ni = 0; ni < 8; ni++) {
                const uint32_t* base = Bsm + (wn * 64 + ni * 8 + g) * 32;
                bf[ni][0] = base[c0];
                bf[ni][1] = base[c2];
            }
            #pragma unroll
            for (int mi = 0; mi < 4; mi++)
                #pragma unroll
                for (int ni = 0; ni < 8; ni++)
                    mma_f16(acc[mi][ni][0], acc[mi][ni][1],
                            acc[mi][ni][2], acc[mi][ni][3],
                            af[mi][0], af[mi][1], af[mi][2], af[mi][3],
                            bf[ni][0], bf[ni][1]);
        }
    }

    // ---- epilogue ----
    if (MODE == 0) {
        __half* C = (__half*)Cv;
        #pragma unroll
        for (int mi = 0; mi < 4; mi++) {
            const int row = bm + wm * 64 + mi * 16 + g;
            #pragma unroll
            for (int ni = 0; ni < 8; ni++) {
                const int col = bn + wn * 64 + ni * 8 + 2 * t;
                *reinterpret_cast<__half2*>(&C[(size_t)row * N + col]) =
                    __floats2half2_rn(acc[mi][ni][0], acc[mi][ni][1]);
                *reinterpret_cast<__half2*>(&C[(size_t)(row + 8) * N + col]) =
                    __floats2half2_rn(acc[mi][ni][2], acc[mi][ni][3]);
            }
        }
    } else if (MODE == 1) {
        __half* C = (__half*)Cv;
        const float aL = alpha * 1.4426950408889634f;   // alpha * log2(e)
        #pragma unroll
        for (int mi = 0; mi < 4; mi++) {
            const int row = bm + wm * 64 + mi * 16 + g;
            float sr0 = 0.0f, sr1 = 0.0f;
            #pragma unroll
            for (int ni = 0; ni < 8; ni++) {
                const int col = bn + wn * 64 + ni * 8 + 2 * t;
                float v0, v1, v2, v3;
                if (ni & 1) {                 // FMA pipe
                    v0 = ex2_fma(acc[mi][ni][0] * aL);
                    v1 = ex2_fma(acc[mi][ni][1] * aL);
                    v2 = ex2_fma(acc[mi][ni][2] * aL);
                    v3 = ex2_fma(acc[mi][ni][3] * aL);
                } else {                      // MUFU pipe
                    v0 = ex2_mufu(acc[mi][ni][0] * aL);
                    v1 = ex2_mufu(acc[mi][ni][1] * aL);
                    v2 = ex2_mufu(acc[mi][ni][2] * aL);
                    v3 = ex2_mufu(acc[mi][ni][3] * aL);
                }
                *reinterpret_cast<__half2*>(&C[(size_t)row * N + col]) =
                    __floats2half2_rn(v0, v1);
                *reinterpret_cast<__half2*>(&C[(size_t)(row + 8) * N + col]) =
                    __floats2half2_rn(v2, v3);
                sr0 += v0 + v1;
                sr1 += v2 + v3;
            }
            // sum over the 4 t-lanes (same g)
            sr0 += __shfl_xor_sync(0xFFFFFFFF, sr0, 1);
            sr0 += __shfl_xor_sync(0xFFFFFFFF, sr0, 2);
            sr1 += __shfl_xor_sync(0xFFFFFFFF, sr1, 1);
            sr1 += __shfl_xor_sync(0xFFFFFFFF, sr1, 2);
            if (t == 0) {
                part[(size_t)row * 64 + bx * 2 + wn]       = sr0;
                part[(size_t)(row + 8) * 64 + bx * 2 + wn] = sr1;
            }
        }
    } else {
        float* C = (float*)Cv;
        #pragma unroll
        for (int mi = 0; mi < 4; mi++) {
            const int lr  = wm * 64 + mi * 16 + g;
            const int row = bm + lr;
            const float s0 = rsm[lr];
            const float s1 = rsm[lr + 8];
            #pragma unroll
            for (int ni = 0; ni < 8; ni++) {
                const int col = bn + wn * 64 + ni * 8 + 2 * t;
                *reinterpret_cast<float2*>(&C[(size_t)row * N + col]) =
                    make_float2(acc[mi][ni][0] * s0, acc[mi][ni][1] * s0);
                *reinterpret_cast<float2*>(&C[(size_t)(row + 8) * N + col]) =
                    make_float2(acc[mi][ni][2] * s1, acc[mi][ni][3] * s1);
            }
        }
    }
}

// Fused Q/K/V projections (fp16 out), blockIdx.z selects weight/output.
__global__ void __launch_bounds__(128, 2) proj_k(
    const __half* __restrict__ Xh,
    const __half* __restrict__ B0, const __half* __restrict__ B1,
    const __half* __restrict__ B2,
    __half* __restrict__ C0, __half* __restrict__ C1, __half* __restrict__ C2)
{
    const int z = blockIdx.z;
    const __half* B = (z == 0) ? B0 : (z == 1) ? B1 : B2;
    __half*       C = (z == 0) ? C0 : (z == 1) ? C1 : C2;
    gemm_body<0>(Xh, B, C, EMB, EMB, 1.0f, nullptr,
                 blockIdx.y * 128, blockIdx.x * 128, blockIdx.x);
}

// Score GEMM with fused exp + partial row sums.
__global__ void __launch_bounds__(128, 2) score_k(
    const __half* __restrict__ Q, const __half* __restrict__ Kh,
    __half* __restrict__ Sh, float* __restrict__ part)
{
    gemm_body<1>(Q, Kh, Sh, SEQ, EMB, 0.03125f, part,
                 blockIdx.y * 128, blockIdx.x * 128, blockIdx.x);
}

// PV GEMM; reciprocal row sums computed in-kernel from partials.
__global__ void __launch_bounds__(128, 2) pv_k(
    const __half* __restrict__ Sh, const __half* __restrict__ Vt,
    float* __restrict__ out, float* __restrict__ part)
{
    gemm_body<2>(Sh, Vt, out, EMB, SEQ, 1.0f, part,
                 blockIdx.y * 128, blockIdx.x * 128, blockIdx.x);
}

// ---------------------------------------------------------------------------
// Fused prep: z<3 -> transpose+convert weight z; z==3 -> convert x to fp16.
// grid (32, 32, 4), block (32, 8).
// ---------------------------------------------------------------------------
__global__ void __launch_bounds__(256) prep_k(
    const float* __restrict__ x,
    const float* __restrict__ Wq, const float* __restrict__ Wk,
    const float* __restrict__ Wv,
    __half* __restrict__ Xh,
    __half* __restrict__ Tq, __half* __restrict__ Tk, __half* __restrict__ Tv)
{
    const int z = blockIdx.z;
    const int xx = threadIdx.x, yy = threadIdx.y;   // 32 x 8

    if (z == 3) {
        // convert x: block covers rows by*128 .. +127, cols bx*32 .. +31
        const int bx = blockIdx.x * 32, by = blockIdx.y * 128;
        #pragma unroll
        for (int j = 0; j < 16; j++) {
            const int row = by + yy + j * 8;
            const int col = bx + xx;
            Xh[(size_t)row * EMB + col] =
                __float2half(x[(size_t)row * EMB + col]);
        }
        return;
    }

    __shared__ float tbuf[32][33];
    const float* in = (z == 0) ? Wq : (z == 1) ? Wk : Wv;
    __half*     out = (z == 0) ? Tq : (z == 1) ? Tk : Tv;

    const int bx = blockIdx.x * 32, by = blockIdx.y * 32;
    #pragma unroll
    for (int j = 0; j < 32; j += 8)
        tbuf[yy + j][xx] = in[(size_t)(by + yy + j) * EMB + bx + xx];
    __syncthreads();
    #pragma unroll
    for (int j = 0; j < 32; j += 8)
        out[(size_t)(bx + yy + j) * EMB + by + xx] =
            __float2half(tbuf[xx][yy + j]);
}

// ---------------------------------------------------------------------------
// fp16 transpose (V -> V^T)
// ---------------------------------------------------------------------------
__global__ void __launch_bounds__(256) htrans_k(const __half* __restrict__ in,
                                                __half* __restrict__ out,
                                                int R, int C)
{
    __shared__ __half t[32][34];
    const int bx = blockIdx.x * 32, by = blockIdx.y * 32;
    const int x = threadIdx.x, y = threadIdx.y;
    #pragma unroll
    for (int j = 0; j < 32; j += 8)
        t[y + j][x] = in[(size_t)(by + y + j) * C + bx + x];
    __syncthreads();
    #pragma unroll
    for (int j = 0; j < 32; j += 8)
        out[(size_t)(bx + y + j) * R + by + x] = t[x][y + j];
}

// ---------------------------------------------------------------------------
extern "C" void kernel_launch(void* const* d_in, const int* in_sizes, int n_in,
                              void* d_out, int out_size)
{
    const float* x  = (const float*)d_in[0];
    const float* Wq = (const float*)d_in[1];
    const float* Wk = (const float*)d_in[2];
    const float* Wv = (const float*)d_in[3];
    float* out = (float*)d_out;

    __half *Xh, *Wqt, *Wkt, *Wvt, *Qh, *Kh, *Vh, *Vt, *Sh;
    float *Part;
    cudaGetSymbolAddress((void**)&Xh,  g_Xh);
    cudaGetSymbolAddress((void**)&Wqt, g_Wqt);
    cudaGetSymbolAddress((void**)&Wkt, g_Wkt);
    cudaGetSymbolAddress((void**)&Wvt, g_Wvt);
    cudaGetSymbolAddress((void**)&Qh,  g_Qh);
    cudaGetSymbolAddress((void**)&Kh,  g_Kh);
    cudaGetSymbolAddress((void**)&Vh,  g_Vh);
    cudaGetSymbolAddress((void**)&Vt,  g_Vt);
    cudaGetSymbolAddress((void**)&Sh,  g_Sh);
    cudaGetSymbolAddress((void**)&Part, g_part);

    cudaFuncSetAttribute(proj_k,
        cudaFuncAttributeMaxDynamicSharedMemorySize, GEMM_DYNSMEM);
    cudaFuncSetAttribute(score_k,
        cudaFuncAttributeMaxDynamicSharedMemorySize, GEMM_DYNSMEM);
    cudaFuncSetAttribute(pv_k,
        cudaFuncAttributeMaxDynamicSharedMemorySize, GEMM_DYNSMEM);

    // Fused prep: x convert + 3 weight transposes in one launch.
    prep_k<<<dim3(32, 32, 4), dim3(32, 8)>>>(x, Wq, Wk, Wv, Xh, Wqt, Wkt, Wvt);

    const dim3 blk(128);
    const dim3 gProj(EMB / 128, SEQ / 128, 3);
    const dim3 gOne (EMB / 128, SEQ / 128);
    const dim3 gScore(SEQ / 128, SEQ / 128);
    const dim3 tblk(32, 8);
    const dim3 gVt(EMB / 32, SEQ / 32);

    // Projections (NT, fp16 out).
    proj_k<<<gProj, blk, GEMM_DYNSMEM>>>(Xh, Wqt, Wkt, Wvt, Qh, Kh, Vh);

    // V^T for the NT PV GEMM.
    htrans_k<<<gVt, tblk>>>(Vh, Vt, SEQ, EMB);

    // Scores + fused exp (fp16 out) + deterministic partial row sums.
    score_k<<<gScore, blk, GEMM_DYNSMEM>>>(Qh, Kh, Sh, Part);

    // Output: out = diag(1/rowsum) * (expS @ Vt^T); rsum fused in prologue.
    pv_k<<<gOne, blk, GEMM_DYNSMEM>>>(Sh, Vt, out, Part);
}